// round 5
// baseline (speedup 1.0000x reference)
#include <cuda_runtime.h>
#include <math.h>

#define BB 8
#define NNODE 1024
#define FD 128
#define GD 64
#define EC 2
#define NH 4
#define NEDGE 16384
#define L0D 256
#define ROWS (BB*NNODE)   // 8192

// ---------------- scratch ----------------
__device__ unsigned g_deg[16*1024];
__device__ unsigned g_rowptr[16*1024];
__device__ unsigned g_cur[16*1024];
__device__ unsigned short g_edges[16*NEDGE];
__device__ float g_Wh[(size_t)ROWS*512];             // [bn][e*256+h*64+g]
__device__ float g_qv[ROWS*16];                      // [bn][ q:e*4+h | 8+v:e*4+h ]
__device__ float g_W2[512*128];                      // packed Ws  [col][f]
__device__ float g_Wqv[16*128];                      // packed Wq/Wv [col][f]
__device__ float g_Xsum[BB*FD];
__device__ float g_Swh[BB*512];                      // [b][col]
__device__ float g_Hcat[(size_t)ROWS*512];
__device__ float g_T1[ROWS*FD];
__device__ float g_U[ROWS*L0D];
__device__ float g_T3[ROWS*FD];
// stats: [0:128) sum1 [128:256) sq1 [256:512) sum2 [512:768) sq2 [768:896) sum3 [896:1024) sq3
__device__ float g_stats[1024];

// ---------------- CSR build ----------------
__global__ void k_init() {
    int i = blockIdx.x * blockDim.x + threadIdx.x;
    if (i < 16384) g_deg[i] = 0u;
    if (i < 1024) g_stats[i] = 0.f;
}

__global__ void k_count(const int* __restrict__ A) {
    int idx = blockIdx.x * blockDim.x + threadIdx.x;   // 262144
    int be = idx >> 14, i = idx & (NEDGE - 1);
    int src = A[(be * 2 + 0) * NEDGE + i];
    atomicAdd(&g_deg[be * 1024 + src], 1u);
}

__global__ void k_scan() {
    __shared__ unsigned s[1024];
    int be = blockIdx.x, t = threadIdx.x;
    unsigned d = g_deg[be * 1024 + t];
    s[t] = d;
    __syncthreads();
    for (int off = 1; off < 1024; off <<= 1) {
        unsigned v = (t >= off) ? s[t - off] : 0u;
        __syncthreads();
        s[t] += v;
        __syncthreads();
    }
    unsigned start = be * NEDGE + s[t] - d;
    g_rowptr[be * 1024 + t] = start;
    g_cur[be * 1024 + t] = start;
}

__global__ void k_place(const int* __restrict__ A) {
    int idx = blockIdx.x * blockDim.x + threadIdx.x;
    int be = idx >> 14, i = idx & (NEDGE - 1);
    int src = A[(be * 2 + 0) * NEDGE + i];
    int dst = A[(be * 2 + 1) * NEDGE + i];
    unsigned pos = atomicAdd(&g_cur[be * 1024 + src], 1u);
    g_edges[pos] = (unsigned short)dst;
}

// ---------------- weight packing & small precompute ----------------
__global__ void k_pack(const float* __restrict__ Ws, const float* __restrict__ Wq,
                       const float* __restrict__ Wv) {
    int idx = blockIdx.x * blockDim.x + threadIdx.x;
    if (idx < 512 * 128) {
        int col = idx >> 7, f = idx & 127;
        int e = col >> 8, rem = col & 255, h = rem >> 6, g = rem & 63;
        g_W2[idx] = Ws[((size_t)e * 512 + h * 128 + f) * GD + g];
    } else if (idx < 512 * 128 + 16 * 128) {
        int i2 = idx - 512 * 128;
        int col = i2 >> 7, f = i2 & 127;
        if (col < 8) {
            int e = col >> 2, h = col & 3;
            g_Wqv[i2] = Wq[e * 512 + h * 128 + f];
        } else {
            int c = col - 8, e = c >> 2, h = c & 3;
            g_Wqv[i2] = Wv[e * 512 + h * 128 + f];
        }
    }
}

__global__ void k_xsum(const float* __restrict__ X) {
    __shared__ float sh[512];
    int b = blockIdx.x, t = threadIdx.x, f = t & 127, nl = t >> 7;
    float s = 0.f;
    for (int n = nl; n < NNODE; n += 4) s += X[((size_t)b * NNODE + n) * FD + f];
    sh[t] = s;
    __syncthreads();
    if (t < 128) g_Xsum[b * FD + t] = sh[t] + sh[t + 128] + sh[t + 256] + sh[t + 384];
}

__global__ void k_swh() {
    __shared__ float sx[128];
    int b = blockIdx.x, col = threadIdx.x;
    if (col < 128) sx[col] = g_Xsum[b * FD + col];
    __syncthreads();
    float s = 0.f;
#pragma unroll 4
    for (int f = 0; f < 128; f++) s += sx[f] * g_W2[col * 128 + f];
    g_Swh[b * 512 + col] = s;
}

// qv[bn][0..15]
__global__ __launch_bounds__(256) void k_qv2(const float* __restrict__ X) {
    __shared__ float sX[64][129];
    __shared__ float sW[16][128];
    int t = threadIdx.x;
    int row0 = blockIdx.x * 64;
    for (int i = t; i < 64 * 128; i += 256) {
        int r = i >> 7, f = i & 127;
        sX[r][f] = X[(size_t)(row0 + r) * FD + f];
    }
    for (int i = t; i < 16 * 128; i += 256) sW[i >> 7][i & 127] = g_Wqv[i];
    __syncthreads();
    int row = t & 63, cg = (t >> 6) * 4;
    float acc[4] = {0.f, 0.f, 0.f, 0.f};
#pragma unroll 4
    for (int f = 0; f < 128; f++) {
        float a = sX[row][f];
#pragma unroll
        for (int c = 0; c < 4; c++) acc[c] += a * sW[cg + c][f];
    }
#pragma unroll
    for (int c = 0; c < 4; c++) g_qv[(size_t)(row0 + row) * 16 + cg + c] = acc[c];
}

// ---------------- 8x8 register-blocked GEMM ----------------
// C[8192][NC] = A[8192][K] @ W[NC][K]^T
// PH0: A=X           W=g_W2  C=g_Wh  K=128 NC=512  (no stats)
// PH1: A=g_Hcat      W=Wemb  C=g_T1  K=512 NC=128  epi 0.5*relu+0.5*X, stats->T1
// PH2: A=bn(g_T1)    W=Wl0   C=g_U   K=128 NC=256  stats->U
// PH3: A=elu(bn(g_U))W=Wl1   C=g_T3  K=256 NC=128  epi +bn(T1), stats->T3
template <int PH>
__global__ __launch_bounds__(128) void k_gemm(const float* __restrict__ ext_w,
                                              const float* __restrict__ ext_x) {
    constexpr int K  = (PH == 1) ? 512 : (PH == 3) ? 256 : 128;
    constexpr int NC = (PH == 0) ? 512 : (PH == 2) ? 256 : 128;
    constexpr bool STATS = (PH >= 1);
    // A-transform stats offsets (PH2 reads T1 stats, PH3 reads U stats)
    constexpr int ASUM = (PH == 2) ? 0 : 256;
    constexpr int ASQ  = (PH == 2) ? 128 : 512;
    // output stats offsets
    constexpr int OSUM = (PH == 1) ? 0 : (PH == 2) ? 256 : 768;
    constexpr int OSQ  = (PH == 1) ? 128 : (PH == 2) ? 512 : 896;

    const float* Am = (PH == 0) ? ext_x : (PH == 1) ? g_Hcat : (PH == 2) ? g_T1 : g_U;
    const float* Wm = (PH == 0) ? g_W2 : ext_w;
    float* Cm       = (PH == 0) ? g_Wh : (PH == 1) ? g_T1 : (PH == 2) ? g_U : g_T3;

    __shared__ float sA[2][16][128];
    __shared__ float sB[2][16][64];
    __shared__ float s_mu[256], s_rs[256];
    __shared__ float s_emu[64], s_ers[64];

    int t = threadIdx.x;
    int r0 = blockIdx.x * 128, c0 = blockIdx.y * 64;
    int tr = t >> 3, tc = t & 7;

    if (PH == 2 || PH == 3) {
        for (int k = t; k < K; k += 128) {
            float mu = g_stats[ASUM + k] * (1.f / 8192.f);
            float var = g_stats[ASQ + k] * (1.f / 8192.f) - mu * mu;
            s_mu[k] = mu;
            s_rs[k] = rsqrtf(var + 1e-5f);
        }
    }
    if (PH == 3 && t < 64) {
        int cg = c0 + t;
        float mu = g_stats[cg] * (1.f / 8192.f);
        float var = g_stats[128 + cg] * (1.f / 8192.f) - mu * mu;
        s_emu[t] = mu;
        s_ers[t] = rsqrtf(var + 1e-5f);
    }
    if (PH >= 2) __syncthreads();   // FIX: s_mu/s_rs must be visible before prologue transform

    const float* aptr = Am + (size_t)(r0 + t) * K;
    int bcol = t & 63, bk = (t >> 6) * 8;
    const float* bptr = Wm + (size_t)(c0 + bcol) * K + bk;

    float acc[8][8] = {};
    float4 ra[4];
    float4 rb[2];

    // prologue: load chunk 0
#pragma unroll
    for (int q = 0; q < 4; q++) ra[q] = *(const float4*)(aptr + q * 4);
    rb[0] = *(const float4*)(bptr);
    rb[1] = *(const float4*)(bptr + 4);
    if (PH == 2 || PH == 3) {
#pragma unroll
        for (int q = 0; q < 4; q++) {
            float* f = (float*)&ra[q];
#pragma unroll
            for (int z = 0; z < 4; z++) {
                int k = q * 4 + z;
                float x = (f[z] - s_mu[k]) * s_rs[k];
                if (PH == 3) x = x > 0.f ? x : expm1f(x);
                f[z] = x;
            }
        }
    }
#pragma unroll
    for (int q = 0; q < 4; q++) {
        float* f = (float*)&ra[q];
#pragma unroll
        for (int z = 0; z < 4; z++) sA[0][q * 4 + z][t] = f[z];
    }
#pragma unroll
    for (int q = 0; q < 2; q++) {
        float* f = (float*)&rb[q];
#pragma unroll
        for (int z = 0; z < 4; z++) sB[0][bk + q * 4 + z][bcol] = f[z];
    }
    __syncthreads();

    constexpr int NKC = K / 16;
    for (int c = 0; c < NKC; c++) {
        int cur = c & 1, nxt = cur ^ 1;
        if (c + 1 < NKC) {
            int kc = (c + 1) * 16;
#pragma unroll
            for (int q = 0; q < 4; q++) ra[q] = *(const float4*)(aptr + kc + q * 4);
            rb[0] = *(const float4*)(bptr + kc);
            rb[1] = *(const float4*)(bptr + kc + 4);
            if (PH == 2 || PH == 3) {
#pragma unroll
                for (int q = 0; q < 4; q++) {
                    float* f = (float*)&ra[q];
#pragma unroll
                    for (int z = 0; z < 4; z++) {
                        int k = kc + q * 4 + z;
                        float x = (f[z] - s_mu[k]) * s_rs[k];
                        if (PH == 3) x = x > 0.f ? x : expm1f(x);
                        f[z] = x;
                    }
                }
            }
        }
#pragma unroll
        for (int k = 0; k < 16; k++) {
            float4 a0 = *(const float4*)&sA[cur][k][tr * 8];
            float4 a1 = *(const float4*)&sA[cur][k][tr * 8 + 4];
            float4 b0 = *(const float4*)&sB[cur][k][tc * 8];
            float4 b1 = *(const float4*)&sB[cur][k][tc * 8 + 4];
            float av[8] = {a0.x, a0.y, a0.z, a0.w, a1.x, a1.y, a1.z, a1.w};
            float bv[8] = {b0.x, b0.y, b0.z, b0.w, b1.x, b1.y, b1.z, b1.w};
#pragma unroll
            for (int i = 0; i < 8; i++)
#pragma unroll
                for (int j = 0; j < 8; j++) acc[i][j] += av[i] * bv[j];
        }
        if (c + 1 < NKC) {
#pragma unroll
            for (int q = 0; q < 4; q++) {
                float* f = (float*)&ra[q];
#pragma unroll
                for (int z = 0; z < 4; z++) sA[nxt][q * 4 + z][t] = f[z];
            }
#pragma unroll
            for (int q = 0; q < 2; q++) {
                float* f = (float*)&rb[q];
#pragma unroll
                for (int z = 0; z < 4; z++) sB[nxt][bk + q * 4 + z][bcol] = f[z];
            }
        }
        __syncthreads();
    }

    // epilogue
    float colsum[8] = {}, colsq[8] = {};
#pragma unroll
    for (int rr = 0; rr < 8; rr++) {
        size_t row = r0 + tr * 8 + rr;
        int cgb = c0 + tc * 8;
        float v[8];
#pragma unroll
        for (int cc = 0; cc < 8; cc++) v[cc] = acc[rr][cc];
        if (PH == 1) {
#pragma unroll
            for (int cc = 0; cc < 8; cc++) {
                float x = ext_x[row * FD + cgb + cc];
                v[cc] = 0.5f * fmaxf(v[cc], 0.f) + 0.5f * x;
            }
        }
        if (PH == 3) {
#pragma unroll
            for (int cc = 0; cc < 8; cc++) {
                float tv = g_T1[row * FD + cgb + cc];
                v[cc] += (tv - s_emu[tc * 8 + cc]) * s_ers[tc * 8 + cc];
            }
        }
        *(float4*)&Cm[row * NC + cgb]     = make_float4(v[0], v[1], v[2], v[3]);
        *(float4*)&Cm[row * NC + cgb + 4] = make_float4(v[4], v[5], v[6], v[7]);
        if (STATS) {
#pragma unroll
            for (int cc = 0; cc < 8; cc++) { colsum[cc] += v[cc]; colsq[cc] += v[cc] * v[cc]; }
        }
    }
    if (STATS) {
        __syncthreads();
        float* s_sum = &sA[0][0][0];          // 1024 floats
        float* s_sq  = s_sum + 1024;
#pragma unroll
        for (int cc = 0; cc < 8; cc++) {
            s_sum[tr * 64 + tc * 8 + cc] = colsum[cc];
            s_sq[tr * 64 + tc * 8 + cc]  = colsq[cc];
        }
        __syncthreads();
        if (t < 64) {
            float s = 0.f, q = 0.f;
#pragma unroll
            for (int i = 0; i < 16; i++) { s += s_sum[i * 64 + t]; q += s_sq[i * 64 + t]; }
            atomicAdd(&g_stats[OSUM + c0 + t], s);
            atomicAdd(&g_stats[OSQ + c0 + t], q);
        }
    }
}

// ---------------- sparse attention ----------------
__global__ __launch_bounds__(256) void k_attn() {
    __shared__ unsigned short s_m[256];
    __shared__ int s_um[256];
    __shared__ float s_uc[256];
    __shared__ float s_w[256][4];
    __shared__ int s_cnt;
    int bn = blockIdx.x;
    int b = bn >> 10, n = bn & 1023;
    int t = threadIdx.x;
    int h = t >> 6, g = t & 63;
    for (int e = 0; e < EC; e++) {
        int r = (b * EC + e) * 1024 + n;
        unsigned start = g_rowptr[r];
        int len = (int)g_deg[r];
        if (len > 256) len = 256;
        if (t == 0) s_cnt = 0;
        for (int j = t; j < len; j += 256) s_m[j] = g_edges[start + j];
        __syncthreads();
        if (t < len) {
            int m = s_m[t];
            int c = 0;
            bool own = true;
            for (int i2 = 0; i2 < len; i2++) {
                int mi = s_m[i2];
                if (mi == m) { c++; if (i2 < t) own = false; }
            }
            if (own) { int slot = atomicAdd(&s_cnt, 1); s_um[slot] = m; s_uc[slot] = (float)c; }
        }
        __syncthreads();
        int cnt = s_cnt;
        for (int jj = t; jj < cnt * 4; jj += 256) {
            int j = jj >> 2, hh = jj & 3;
            float qn = g_qv[(size_t)bn * 16 + e * 4 + hh];
            float vm = g_qv[((size_t)b * NNODE + s_um[j]) * 16 + 8 + e * 4 + hh];
            float s = qn * vm * s_uc[j];
            float l = s >= 0.f ? s : 0.01f * s;
            s_w[j][hh] = expf(l) - 1.f;
        }
        __syncthreads();
        const float* Whb = g_Wh + (size_t)b * NNODE * 512 + e * 256 + h * 64 + g;
        float num = 0.f, den = 0.f;
        int j = 0;
        for (; j + 4 <= cnt; j += 4) {
            float w0 = s_w[j][h], w1 = s_w[j + 1][h], w2 = s_w[j + 2][h], w3 = s_w[j + 3][h];
            float x0 = __ldg(&Whb[(size_t)s_um[j] * 512]);
            float x1 = __ldg(&Whb[(size_t)s_um[j + 1] * 512]);
            float x2 = __ldg(&Whb[(size_t)s_um[j + 2] * 512]);
            float x3 = __ldg(&Whb[(size_t)s_um[j + 3] * 512]);
            num += w0 * x0 + w1 * x1 + w2 * x2 + w3 * x3;
            den += w0 + w1 + w2 + w3;
        }
        for (; j < cnt; j++) {
            float w = s_w[j][h];
            num += w * __ldg(&Whb[(size_t)s_um[j] * 512]);
            den += w;
        }
        float out = (g_Swh[b * 512 + e * 256 + h * 64 + g] + num) / (1024.f + den);
        g_Hcat[(size_t)bn * 512 + h * 128 + e * 64 + g] = out;
        __syncthreads();
    }
}

// ---------------- final normalization ----------------
__global__ void k_norm3(float* __restrict__ out) {
    int i = blockIdx.x * blockDim.x + threadIdx.x;
    int col = i & 127;
    float mu = g_stats[768 + col] * (1.f / 8192.f);
    float var = g_stats[896 + col] * (1.f / 8192.f) - mu * mu;
    float rs = rsqrtf(var + 1e-5f);
    out[i] = (g_T3[i] - mu) * rs;
}

// ---------------- launch ----------------
extern "C" void kernel_launch(void* const* d_in, const int* in_sizes, int n_in,
                              void* d_out, int out_size) {
    const int*   A    = (const int*)d_in[0];
    const float* X    = (const float*)d_in[1];
    const float* Ws   = (const float*)d_in[2];
    const float* Wq   = (const float*)d_in[3];
    const float* Wv   = (const float*)d_in[4];
    const float* Wemb = (const float*)d_in[5];
    const float* Wl0  = (const float*)d_in[6];
    const float* Wl1  = (const float*)d_in[7];
    float* out = (float*)d_out;

    k_init<<<34, 512>>>();
    k_count<<<512, 512>>>(A);
    k_scan<<<16, 1024>>>();
    k_place<<<512, 512>>>(A);
    k_pack<<<66, 1024>>>(Ws, Wq, Wv);
    k_gemm<0><<<dim3(64, 8), 128>>>(nullptr, X);     // Wh
    k_qv2<<<128, 256>>>(X);
    k_xsum<<<8, 512>>>(X);
    k_swh<<<8, 512>>>();
    k_attn<<<8192, 256>>>();
    k_gemm<1><<<dim3(64, 2), 128>>>(Wemb, X);        // T1 + stats
    k_gemm<2><<<dim3(64, 4), 128>>>(Wl0, nullptr);   // U  + stats (A=bn(T1))
    k_gemm<3><<<dim3(64, 2), 128>>>(Wl1, nullptr);   // T3 + stats (A=elu(bn(U)), epi +bn(T1))
    k_norm3<<<4096, 256>>>(out);
}

// round 8
// speedup vs baseline: 1.3281x; 1.3281x over previous
#include <cuda_runtime.h>
#include <cuda_bf16.h>
#include <cstdint>
#include <math.h>

typedef unsigned int u32;

#define BB 8
#define NNODE 1024
#define FD 128
#define GD 64
#define EC 2
#define NH 4
#define NEDGE 16384
#define L0D 256
#define ROWS (BB*NNODE)

// ---------------- scratch ----------------
__device__ u32 g_deg[16*1024];
__device__ u32 g_rowptr[16*1024];
__device__ u32 g_cur[16*1024];
__device__ unsigned short g_edges[16*NEDGE];
__device__ float g_Wh[(size_t)ROWS*512];
__device__ float g_qv[ROWS*16];
__device__ float g_Wqv[16*128];
__device__ float g_Swh[BB*512];
__device__ float g_T1[ROWS*FD];
__device__ float g_U[ROWS*L0D];
__device__ float g_T3[ROWS*FD];
__device__ float g_stats[1024];
// split-bf16 A matrices [Ahi | Ahi | Alo] along K
__device__ __align__(16) __nv_bfloat16 g_A0[(size_t)ROWS*384];
__device__ __align__(16) __nv_bfloat16 g_A1[(size_t)ROWS*1536];
__device__ __align__(16) __nv_bfloat16 g_A2[(size_t)ROWS*384];
__device__ __align__(16) __nv_bfloat16 g_A3[(size_t)ROWS*768];
// split-bf16 B matrices [Bhi | Blo | Bhi] along K
__device__ __align__(16) __nv_bfloat16 g_B0[512*384];
__device__ __align__(16) __nv_bfloat16 g_B1[128*1536];
__device__ __align__(16) __nv_bfloat16 g_B2[256*384];
__device__ __align__(16) __nv_bfloat16 g_B3[128*768];

// ---------------- asm helpers ----------------
__device__ __forceinline__ void cpa16(u32 s, const void* g) {
    asm volatile("cp.async.cg.shared.global [%0], [%1], 16;\n" :: "r"(s), "l"(g));
}
__device__ __forceinline__ void cp_commit() { asm volatile("cp.async.commit_group;\n"); }
template <int N>
__device__ __forceinline__ void cp_wait() {
    asm volatile("cp.async.wait_group %0;\n" :: "n"(N));
}
__device__ __forceinline__ void ldsm4(u32& r0, u32& r1, u32& r2, u32& r3, u32 a) {
    asm volatile("ldmatrix.sync.aligned.m8n8.x4.shared.b16 {%0,%1,%2,%3}, [%4];\n"
                 : "=r"(r0), "=r"(r1), "=r"(r2), "=r"(r3) : "r"(a));
}
__device__ __forceinline__ void mma16816(float* d, const u32* a, const u32* b) {
    asm volatile("mma.sync.aligned.m16n8k16.row.col.f32.bf16.bf16.f32 "
                 "{%0,%1,%2,%3},{%4,%5,%6,%7},{%8,%9},{%0,%1,%2,%3};\n"
                 : "+f"(d[0]), "+f"(d[1]), "+f"(d[2]), "+f"(d[3])
                 : "r"(a[0]), "r"(a[1]), "r"(a[2]), "r"(a[3]), "r"(b[0]), "r"(b[1]));
}
__device__ __forceinline__ void split2(float x, __nv_bfloat16& hi, __nv_bfloat16& lo) {
    hi = __float2bfloat16(x);
    lo = __float2bfloat16(x - __bfloat162float(hi));
}

template <int K3>
__device__ __forceinline__ void load_stage(const __nv_bfloat16* Am, const __nv_bfloat16* Bm,
                                           int r0, int c0, u32 sAu, u32 sBu,
                                           int t, int c, int buf) {
#pragma unroll
    for (int i = 0; i < 2; i++) {
        int slot = t * 2 + i;
        int row = slot >> 2;
        int part = slot & 3;
        cpa16(sAu + (u32)(buf * 5120 + row * 40 + part * 8) * 2,
              Am + (size_t)(r0 + row) * K3 + c * 32 + part * 8);
        cpa16(sBu + (u32)(buf * 5120 + row * 40 + part * 8) * 2,
              Bm + (size_t)(c0 + row) * K3 + c * 32 + part * 8);
    }
}

// ---------------- CSR build ----------------
__global__ void k_init() {
    int i = blockIdx.x * blockDim.x + threadIdx.x;
    if (i < 16384) g_deg[i] = 0u;
    if (i < 1024) g_stats[i] = 0.f;
}
__global__ void k_count(const int* __restrict__ A) {
    int idx = blockIdx.x * blockDim.x + threadIdx.x;
    int be = idx >> 14;
    int i = idx & (NEDGE - 1);
    atomicAdd(&g_deg[be * 1024 + A[(be * 2 + 0) * NEDGE + i]], 1u);
}
__global__ void k_scan() {
    __shared__ u32 s[1024];
    int be = blockIdx.x;
    int t = threadIdx.x;
    u32 d = g_deg[be * 1024 + t];
    s[t] = d;
    __syncthreads();
    for (int off = 1; off < 1024; off <<= 1) {
        u32 v = (t >= off) ? s[t - off] : 0u;
        __syncthreads();
        s[t] += v;
        __syncthreads();
    }
    u32 start = be * NEDGE + s[t] - d;
    g_rowptr[be * 1024 + t] = start;
    g_cur[be * 1024 + t] = start;
}
__global__ void k_place(const int* __restrict__ A) {
    int idx = blockIdx.x * blockDim.x + threadIdx.x;
    int be = idx >> 14;
    int i = idx & (NEDGE - 1);
    int src = A[(be * 2 + 0) * NEDGE + i];
    int dst = A[(be * 2 + 1) * NEDGE + i];
    u32 pos = atomicAdd(&g_cur[be * 1024 + src], 1u);
    g_edges[pos] = (unsigned short)dst;
}

// ---------------- weight packing (split-bf16 B + fp32 Wqv) ----------------
__global__ void k_packb(const float* __restrict__ Ws, const float* __restrict__ Wemb,
                        const float* __restrict__ Wl0, const float* __restrict__ Wl1,
                        const float* __restrict__ Wq, const float* __restrict__ Wv) {
    int idx = blockIdx.x * blockDim.x + threadIdx.x;
    __nv_bfloat16 hi, lo;
    if (idx < 65536) {                       // B0: 512 x 128 (col = e*256+h*64+g)
        int col = idx >> 7;
        int f = idx & 127;
        int e = col >> 8;
        int rem = col & 255;
        int h = rem >> 6;
        int g = rem & 63;
        split2(Ws[((size_t)e * 512 + h * 128 + f) * GD + g], hi, lo);
        g_B0[col * 384 + f] = hi;
        g_B0[col * 384 + 128 + f] = lo;
        g_B0[col * 384 + 256 + f] = hi;
    } else if (idx < 131072) {               // B1: 128 x 512
        int i2 = idx - 65536;
        int col = i2 >> 9;
        int k = i2 & 511;
        split2(Wemb[col * 512 + k], hi, lo);
        g_B1[col * 1536 + k] = hi;
        g_B1[col * 1536 + 512 + k] = lo;
        g_B1[col * 1536 + 1024 + k] = hi;
    } else if (idx < 163840) {               // B2: 256 x 128
        int i2 = idx - 131072;
        int col = i2 >> 7;
        int k = i2 & 127;
        split2(Wl0[col * 128 + k], hi, lo);
        g_B2[col * 384 + k] = hi;
        g_B2[col * 384 + 128 + k] = lo;
        g_B2[col * 384 + 256 + k] = hi;
    } else if (idx < 196608) {               // B3: 128 x 256
        int i2 = idx - 163840;
        int col = i2 >> 8;
        int k = i2 & 255;
        split2(Wl1[col * 256 + k], hi, lo);
        g_B3[col * 768 + k] = hi;
        g_B3[col * 768 + 256 + k] = lo;
        g_B3[col * 768 + 512 + k] = hi;
    } else if (idx < 198656) {               // Wqv fp32: 16 x 128
        int i2 = idx - 196608;
        int col = i2 >> 7;
        int f = i2 & 127;
        if (col < 8) g_Wqv[i2] = Wq[(col >> 2) * 512 + (col & 3) * 128 + f];
        else {
            int c = col - 8;
            g_Wqv[i2] = Wv[(c >> 2) * 512 + (c & 3) * 128 + f];
        }
    }
}

// split conversions: PH0 X->A0, PH2 bn(T1)->A2, PH3 elu(bn(U))->A3
template <int PH>
__global__ void k_conv(const float* __restrict__ ext) {
    constexpr int C = (PH == 3) ? 256 : 128;
    int idx = blockIdx.x * blockDim.x + threadIdx.x;
    int row = idx / C;
    int k = idx % C;
    float x;
    if (PH == 0) {
        x = ext[idx];
    } else {
        constexpr int SO = (PH == 2) ? 0 : 256;
        constexpr int QO = (PH == 2) ? 128 : 512;
        const float* src = (PH == 2) ? g_T1 : g_U;
        float mu = g_stats[SO + k] * (1.f / 8192.f);
        float var = g_stats[QO + k] * (1.f / 8192.f) - mu * mu;
        x = (src[idx] - mu) * rsqrtf(var + 1e-5f);
        if (PH == 3) x = x > 0.f ? x : expm1f(x);
    }
    __nv_bfloat16 hi, lo;
    split2(x, hi, lo);
    __nv_bfloat16* a = ((PH == 0) ? g_A0 : (PH == 2) ? g_A2 : g_A3) + (size_t)row * 3 * C;
    a[k] = hi;
    a[C + k] = hi;
    a[2 * C + k] = lo;
}

// Swh[b][col] = sum_n Wh[b*1024+n][col]
__global__ void k_swh() {
    int b = blockIdx.x;
    int col = blockIdx.y * 128 + threadIdx.x;
    float s = 0.f;
    const float* p = g_Wh + (size_t)b * 1024 * 512 + col;
    for (int n = 0; n < NNODE; n++) s += p[(size_t)n * 512];
    g_Swh[b * 512 + col] = s;
}

__global__ __launch_bounds__(256) void k_qv2(const float* __restrict__ X) {
    __shared__ float sX[64][129];
    __shared__ float sW[16][128];
    int t = threadIdx.x;
    int row0 = blockIdx.x * 64;
    for (int i = t; i < 64 * 128; i += 256) {
        int r = i >> 7;
        int f = i & 127;
        sX[r][f] = X[(size_t)(row0 + r) * FD + f];
    }
    for (int i = t; i < 16 * 128; i += 256) sW[i >> 7][i & 127] = g_Wqv[i];
    __syncthreads();
    int row = t & 63;
    int cg = (t >> 6) * 4;
    float acc[4] = {0.f, 0.f, 0.f, 0.f};
#pragma unroll 4
    for (int f = 0; f < 128; f++) {
        float a = sX[row][f];
#pragma unroll
        for (int c = 0; c < 4; c++) acc[c] += a * sW[cg + c][f];
    }
#pragma unroll
    for (int c = 0; c < 4; c++) g_qv[(size_t)(row0 + row) * 16 + cg + c] = acc[c];
}

// ---------------- tensor-core GEMM ----------------
template <int PH>
__global__ __launch_bounds__(256) void k_mma(const float* __restrict__ ext_x) {
    constexpr int K3 = (PH == 0) ? 384 : (PH == 1) ? 1536 : (PH == 2) ? 384 : 768;
    constexpr int NC = (PH == 0) ? 512 : (PH == 1) ? 128 : (PH == 2) ? 256 : 128;
    constexpr int NKC = K3 / 32;
    constexpr bool STATS = (PH >= 1);
    constexpr int OSUM = (PH == 1) ? 0 : (PH == 2) ? 256 : 768;
    constexpr int OSQ  = (PH == 1) ? 128 : (PH == 2) ? 512 : 896;

    const __nv_bfloat16* Am = (PH == 0) ? g_A0 : (PH == 1) ? g_A1 : (PH == 2) ? g_A2 : g_A3;
    const __nv_bfloat16* Bm = (PH == 0) ? g_B0 : (PH == 1) ? g_B1 : (PH == 2) ? g_B2 : g_B3;
    float* Cm = (PH == 0) ? g_Wh : (PH == 1) ? g_T1 : (PH == 2) ? g_U : g_T3;

    __shared__ __align__(16) __nv_bfloat16 sA[2][128 * 40];
    __shared__ __align__(16) __nv_bfloat16 sB[2][128 * 40];
    __shared__ float s_emu[128];
    __shared__ float s_ers[128];

    int t = threadIdx.x;
    int lane = t & 31;
    int warp = t >> 5;
    int warpM = warp >> 2;
    int warpN = warp & 3;
    int r0 = blockIdx.x * 128;
    int c0 = blockIdx.y * 128;

    if (PH == 3 && t < 128) {
        float mu = g_stats[t] * (1.f / 8192.f);
        float var = g_stats[128 + t] * (1.f / 8192.f) - mu * mu;
        s_emu[t] = mu;
        s_ers[t] = rsqrtf(var + 1e-5f);
    }
    if (PH == 3) __syncthreads();

    u32 sAu = (u32)__cvta_generic_to_shared(&sA[0][0]);
    u32 sBu = (u32)__cvta_generic_to_shared(&sB[0][0]);

    float acc[4][4][4] = {};

    load_stage<K3>(Am, Bm, r0, c0, sAu, sBu, t, 0, 0);
    cp_commit();

    int a_row = warpM * 64 + (lane & 15);
    int a_col = (lane >> 4) << 3;
    int b_row = warpN * 32 + (lane & 7) + ((lane >> 4) << 3);
    int b_col = ((lane >> 3) & 1) ? 8 : 0;

    for (int c = 0; c < NKC; c++) {
        int buf = c & 1;
        if (c + 1 < NKC) {
            load_stage<K3>(Am, Bm, r0, c0, sAu, sBu, t, c + 1, buf ^ 1);
            cp_commit();
            cp_wait<1>();
        } else {
            cp_wait<0>();
        }
        __syncthreads();
#pragma unroll
        for (int s = 0; s < 2; s++) {
            int k0 = s * 16;
            u32 af[4][4];
#pragma unroll
            for (int mt = 0; mt < 4; mt++) {
                u32 addr = sAu + (u32)(buf * 5120 + (a_row + mt * 16) * 40 + k0 + a_col) * 2;
                ldsm4(af[mt][0], af[mt][1], af[mt][2], af[mt][3], addr);
            }
            u32 bf[4][2];
#pragma unroll
            for (int np = 0; np < 2; np++) {
                u32 addr = sBu + (u32)(buf * 5120 + (b_row + np * 16) * 40 + k0 + b_col) * 2;
                u32 q0, q1, q2, q3;
                ldsm4(q0, q1, q2, q3, addr);
                bf[np * 2][0] = q0;
                bf[np * 2][1] = q1;
                bf[np * 2 + 1][0] = q2;
                bf[np * 2 + 1][1] = q3;
            }
#pragma unroll
            for (int mt = 0; mt < 4; mt++) {
#pragma unroll
                for (int nt = 0; nt < 4; nt++) {
                    mma16816(acc[mt][nt], af[mt], bf[nt]);
                }
            }
        }
        __syncthreads();
    }

    float colsum[8] = {0.f, 0.f, 0.f, 0.f, 0.f, 0.f, 0.f, 0.f};
    float colsq[8]  = {0.f, 0.f, 0.f, 0.f, 0.f, 0.f, 0.f, 0.f};
#pragma unroll
    for (int mt = 0; mt < 4; mt++) {
        int m = r0 + warpM * 64 + mt * 16 + (lane >> 2);
#pragma unroll
        for (int nt = 0; nt < 4; nt++) {
            int cc = c0 + warpN * 32 + nt * 8 + ((lane & 3) << 1);
            float v0 = acc[mt][nt][0];
            float v1 = acc[mt][nt][1];
            float v2 = acc[mt][nt][2];
            float v3 = acc[mt][nt][3];
            if (PH == 1) {
                float2 x0 = *(const float2*)&ext_x[(size_t)m * FD + cc];
                float2 x1 = *(const float2*)&ext_x[(size_t)(m + 8) * FD + cc];
                v0 = 0.5f * fmaxf(v0, 0.f) + 0.5f * x0.x;
                v1 = 0.5f * fmaxf(v1, 0.f) + 0.5f * x0.y;
                v2 = 0.5f * fmaxf(v2, 0.f) + 0.5f * x1.x;
                v3 = 0.5f * fmaxf(v3, 0.f) + 0.5f * x1.y;
            }
            if (PH == 3) {
                float2 t0 = *(const float2*)&g_T1[(size_t)m * FD + cc];
                float2 t1 = *(const float2*)&g_T1[(size_t)(m + 8) * FD + cc];
                v0 += (t0.x - s_emu[cc]) * s_ers[cc];
                v1 += (t0.y - s_emu[cc + 1]) * s_ers[cc + 1];
                v2 += (t1.x - s_emu[cc]) * s_ers[cc];
                v3 += (t1.y - s_emu[cc + 1]) * s_ers[cc + 1];
            }
            *(float2*)&Cm[(size_t)m * NC + cc] = make_float2(v0, v1);
            *(float2*)&Cm[(size_t)(m + 8) * NC + cc] = make_float2(v2, v3);
            if (STATS) {
                colsum[nt * 2] += v0 + v2;
                colsq[nt * 2] += v0 * v0 + v2 * v2;
                colsum[nt * 2 + 1] += v1 + v3;
                colsq[nt * 2 + 1] += v1 * v1 + v3 * v3;
            }
        }
    }
    if (STATS) {
#pragma unroll
        for (int s2 = 0; s2 < 8; s2++) {
#pragma unroll
            for (int off = 4; off < 32; off <<= 1) {
                colsum[s2] += __shfl_xor_sync(0xffffffffu, colsum[s2], off);
                colsq[s2]  += __shfl_xor_sync(0xffffffffu, colsq[s2], off);
            }
        }
        if (lane < 4) {
#pragma unroll
            for (int nt = 0; nt < 4; nt++) {
#pragma unroll
                for (int p = 0; p < 2; p++) {
                    int col = c0 + warpN * 32 + nt * 8 + lane * 2 + p;
                    atomicAdd(&g_stats[OSUM + col], colsum[nt * 2 + p]);
                    atomicAdd(&g_stats[OSQ + col], colsq[nt * 2 + p]);
                }
            }
        }
    }
}

// ---------------- sparse attention ----------------
__global__ __launch_bounds__(256) void k_attn() {
    __shared__ unsigned short s_m[256];
    __shared__ int s_um[256];
    __shared__ float s_uc[256];
    __shared__ float s_w[256][4];
    __shared__ int s_cnt;
    int bn = blockIdx.x;
    int b = bn >> 10;
    int n = bn & 1023;
    int t = threadIdx.x;
    int h = t >> 6;
    int g = t & 63;
    __nv_bfloat16* arow = g_A1 + (size_t)bn * 1536;
    for (int e = 0; e < EC; e++) {
        int r = (b * EC + e) * 1024 + n;
        u32 start = g_rowptr[r];
        int len = (int)g_deg[r];
        if (len > 256) len = 256;
        if (t == 0) s_cnt = 0;
        for (int j = t; j < len; j += 256) s_m[j] = g_edges[start + j];
        __syncthreads();
        if (t < len) {
            int m = s_m[t];
            int c = 0;
            bool own = true;
            for (int i2 = 0; i2 < len; i2++) {
                int mi = s_m[i2];
                if (mi == m) {
                    c++;
                    if (i2 < t) own = false;
                }
            }
            if (own) {
                int slot = atomicAdd(&s_cnt, 1);
                s_um[slot] = m;
                s_uc[slot] = (float)c;
            }
        }
        __syncthreads();
        int cnt = s_cnt;
        for (int jj = t; jj < cnt * 4; jj += 256) {
            int j = jj >> 2;
            int hh = jj & 3;
            float qn = g_qv[(size_t)bn * 16 + e * 4 + hh];
            float vm = g_qv[((size_t)b * NNODE + s_um[j]) * 16 + 8 + e * 4 + hh];
            float s = qn * vm * s_uc[j];
            float l = s >= 0.f ? s : 0.01f * s;
            s_w[j][hh] = expf(l) - 1.f;
        }
        __syncthreads();
        const float* Whb = g_Wh + (size_t)b * NNODE * 512 + e * 256 + h * 64 + g;
        float num = 0.f;
        float den = 0.f;
        for (int j = 0; j < cnt; j++) {
            float w = s_w[j][h];
            num += w * __ldg(&Whb[(size_t)s_um[j] * 512]);
            den += w;
        }
        float outv = (g_Swh[b * 512 + e * 256 + h * 64 + g] + num) / (1024.f + den);
        int col = h * 128 + e * 64 + g;
        __nv_bfloat16 hi, lo;
        split2(outv, hi, lo);
        arow[col] = hi;
        arow[512 + col] = hi;
        arow[1024 + col] = lo;
        __syncthreads();
    }
}

// ---------------- final normalization ----------------
__global__ void k_norm3(float* __restrict__ out) {
    int i = blockIdx.x * blockDim.x + threadIdx.x;
    int col = i & 127;
    float mu = g_stats[768 + col] * (1.f / 8192.f);
    float var = g_stats[896 + col] * (1.f / 8192.f) - mu * mu;
    float rs = rsqrtf(var + 1e-5f);
    out[i] = (g_T3[i] - mu) * rs;
}

// ---------------- launch ----------------
extern "C" void kernel_launch(void* const* d_in, const int* in_sizes, int n_in,
                              void* d_out, int out_size) {
    const int*   A    = (const int*)d_in[0];
    const float* X    = (const float*)d_in[1];
    const float* Ws   = (const float*)d_in[2];
    const float* Wq   = (const float*)d_in[3];
    const float* Wv   = (const float*)d_in[4];
    const float* Wemb = (const float*)d_in[5];
    const float* Wl0  = (const float*)d_in[6];
    const float* Wl1  = (const float*)d_in[7];
    float* out = (float*)d_out;

    k_init<<<34, 512>>>();
    k_count<<<512, 512>>>(A);
    k_scan<<<16, 1024>>>();
    k_place<<<512, 512>>>(A);
    k_packb<<<776, 256>>>(Ws, Wemb, Wl0, Wl1, Wq, Wv);
    k_conv<0><<<4096, 256>>>(X);
    k_mma<0><<<dim3(64, 4), 256>>>(nullptr);
    k_qv2<<<128, 256>>>(X);
    k_swh<<<dim3(8, 4), 128>>>();
    k_attn<<<8192, 256>>>();
    k_mma<1><<<dim3(64, 1), 256>>>(X);
    k_conv<2><<<4096, 256>>>(nullptr);
    k_mma<2><<<dim3(64, 2), 256>>>(nullptr);
    k_conv<3><<<8192, 256>>>(nullptr);
    k_mma<3><<<dim3(64, 1), 256>>>(nullptr);
    k_norm3<<<4096, 256>>>(out);
}